// round 8
// baseline (speedup 1.0000x reference)
#include <cuda_runtime.h>

// ---------------------------------------------------------------------------
// QuantumNet, fully collapsed via Heisenberg propagation of Z0.
//
// O = U^H Z0 U stays in span{Z0, Y0, Z0X1, Y0X1} for any layer count:
//   CNOT01:  Z0->Z0, Y0->Y0X1, Z0X1->Z0X1, Y0X1->Y0
//   RX1(w):  identity on the span (X1 commutes with RX1)
//   RX0(w):  (Z,Y) pairs rotate:  z' = c z - s y,  y' = s z + c y
// On |psi> = RX0(x0) RX1(x1) |00>:  <Z0>=cos x0, <Y0>=-sin x0, <·X1>=0.
// => out = 0.5 + 0.5 z cos(x0) - 0.5 y sin(x0).   (x1 and all RX1 weights
// are irrelevant to the measured observable.)
//
// (z,y) costs ~n_layers*(sincos + 4 FMA): every thread computes it inline
// => single kernel, no prep launch, ~28 regs, full occupancy.
// ---------------------------------------------------------------------------

__global__ void __launch_bounds__(256)
qnet_kernel(const float* __restrict__ x, float* __restrict__ out, int n,
            const float* __restrict__ w, int n_layers) {
    // Backward Heisenberg recurrence (uniform across threads; tiny).
    float z = 1.0f, y = 0.0f, zx = 0.0f, yx = 0.0f;
    for (int l = n_layers - 1; l >= 0; l--) {
        // CNOT conjugation: Y0 <-> Y0X1
        float tmp = y; y = yx; yx = tmp;
        // RX0(w_l0) conjugation rotates both (z,y) and (zx,yx)
        float wl = __ldg(w + 2 * l);
        float s, c;
        __sincosf(wl, &s, &c);
        float z2  = fmaf(c, z,  -s * y);
        float y2  = fmaf(s, z,   c * y);
        float zx2 = fmaf(c, zx, -s * yx);
        float yx2 = fmaf(s, zx,  c * yx);
        z = z2; y = y2; zx = zx2; yx = yx2;
    }
    const float ha = 0.5f * z;     // coeff of cos(x0)
    const float hb = -0.5f * y;    // coeff of sin(x0)

    long long t = (long long)blockIdx.x * blockDim.x + threadIdx.x;
    long long base = t * 8;        // 8 samples per thread

    if (base + 7 < (long long)n) {
        // 4 front-batched LDG.128 (MLP=4), 2 STG.128
        const float4* x4 = (const float4*)x;
        float4 a = x4[t * 4 + 0];  // (x0_0, x1_0, x0_1, x1_1)
        float4 b = x4[t * 4 + 1];
        float4 c = x4[t * 4 + 2];
        float4 d = x4[t * 4 + 3];

        float S, C;
        float4 o0, o1;
        __sincosf(a.x, &S, &C); o0.x = fmaf(ha, C, fmaf(hb, S, 0.5f));
        __sincosf(a.z, &S, &C); o0.y = fmaf(ha, C, fmaf(hb, S, 0.5f));
        __sincosf(b.x, &S, &C); o0.z = fmaf(ha, C, fmaf(hb, S, 0.5f));
        __sincosf(b.z, &S, &C); o0.w = fmaf(ha, C, fmaf(hb, S, 0.5f));
        __sincosf(c.x, &S, &C); o1.x = fmaf(ha, C, fmaf(hb, S, 0.5f));
        __sincosf(c.z, &S, &C); o1.y = fmaf(ha, C, fmaf(hb, S, 0.5f));
        __sincosf(d.x, &S, &C); o1.z = fmaf(ha, C, fmaf(hb, S, 0.5f));
        __sincosf(d.z, &S, &C); o1.w = fmaf(ha, C, fmaf(hb, S, 0.5f));

        float4* out4 = (float4*)out;
        out4[t * 2 + 0] = o0;
        out4[t * 2 + 1] = o1;
    } else {
        for (long long i = base; i < (long long)n; i++) {
            float S, C;
            __sincosf(x[2 * i], &S, &C);
            out[i] = fmaf(ha, C, fmaf(hb, S, 0.5f));
        }
    }
}

extern "C" void kernel_launch(void* const* d_in, const int* in_sizes, int n_in,
                              void* d_out, int out_size) {
    const float* x = (const float*)d_in[0];        // [B, 2] float32
    const float* w = (const float*)d_in[1];        // [N_LAYERS, 2] float32
    float* out = (float*)d_out;                    // [B, 1] float32

    int n = in_sizes[0] / 2;          // samples B
    int n_layers = in_sizes[1] / 2;

    long long threads = ((long long)n + 7) / 8;
    int blocks = (int)((threads + 255) / 256);
    qnet_kernel<<<blocks, 256>>>(x, out, n, w, n_layers);
}

// round 10
// speedup vs baseline: 1.0151x; 1.0151x over previous
#include <cuda_runtime.h>

// ---------------------------------------------------------------------------
// QuantumNet, fully collapsed via Heisenberg propagation of Z0.
//
//   out = 0.5 + ha*cos(x0) + hb*sin(x0)  =  0.5 + r*cos(x0 - phi)
//
// O = U^H Z0 U stays in span{Z0, Y0, Z0X1, Y0X1} for any layer count
// (CNOT: Y0<->Y0X1; RX1: identity on the span; RX0: rotates (z,y) pairs).
// On the encoded state <Z0>=cos x0, <Y0>=-sin x0, all X1 terms vanish.
// x1 and RX1 weights are irrelevant. (Validated in R8: rel_err 1.0e-7.)
//
// Scheduling: the 4 x-loads are issued FIRST; the tiny uniform recurrence
// (plus sqrt/atan2) runs under their DRAM latency. 1 MUFU + 1 FADD + 1 FMA
// per sample. Single kernel, no prep launch.
// ---------------------------------------------------------------------------

__global__ void __launch_bounds__(256)
qnet_kernel(const float* __restrict__ x, float* __restrict__ out, int n,
            const float* __restrict__ w, int n_layers) {
    long long t = (long long)blockIdx.x * blockDim.x + threadIdx.x;
    long long base = t * 8;                    // 8 samples per thread
    const bool full = (base + 7) < (long long)n;

    // ---- 1) Front-batched loads: 4x LDG.128, MLP=4 ----------------------
    float4 a, b, c, d;
    if (full) {
        const float4* x4 = (const float4*)x;
        a = __ldcs(x4 + t * 4 + 0);            // (x0_0, x1_0, x0_1, x1_1)
        b = __ldcs(x4 + t * 4 + 1);
        c = __ldcs(x4 + t * 4 + 2);
        d = __ldcs(x4 + t * 4 + 3);
    }

    // ---- 2) Uniform recurrence, overlapped with load latency ------------
    float z = 1.0f, y = 0.0f, zx = 0.0f, yx = 0.0f;
#pragma unroll 4
    for (int l = n_layers - 1; l >= 0; l--) {
        float tmp = y; y = yx; yx = tmp;       // CNOT: Y0 <-> Y0X1
        float s, cc;
        __sincosf(__ldg(w + 2 * l), &s, &cc);  // RX0(w_l0) conjugation
        float z2  = fmaf(cc, z,  -s * y);
        float y2  = fmaf(s,  z,   cc * y);
        float zx2 = fmaf(cc, zx, -s * yx);
        float yx2 = fmaf(s,  zx,  cc * yx);
        z = z2; y = y2; zx = zx2; yx = yx2;
    }
    const float ha = 0.5f * z;                 // coeff of cos(x0)
    const float hb = -0.5f * y;                // coeff of sin(x0)
    const float r   = sqrtf(fmaf(ha, ha, hb * hb));
    const float phi = atan2f(hb, ha);          // ha*C + hb*S = r*cos(x0-phi)

    // ---- 3) Consume: 1 MUFU.COS + FADD + FMA per sample -----------------
    if (full) {
        float4 o0, o1;
        o0.x = fmaf(r, __cosf(a.x - phi), 0.5f);
        o0.y = fmaf(r, __cosf(a.z - phi), 0.5f);
        o0.z = fmaf(r, __cosf(b.x - phi), 0.5f);
        o0.w = fmaf(r, __cosf(b.z - phi), 0.5f);
        o1.x = fmaf(r, __cosf(c.x - phi), 0.5f);
        o1.y = fmaf(r, __cosf(c.z - phi), 0.5f);
        o1.z = fmaf(r, __cosf(d.x - phi), 0.5f);
        o1.w = fmaf(r, __cosf(d.z - phi), 0.5f);
        float4* out4 = (float4*)out;
        __stcs(out4 + t * 2 + 0, o0);
        __stcs(out4 + t * 2 + 1, o1);
    } else {
        for (long long i = base; i < (long long)n; i++)
            out[i] = fmaf(r, __cosf(x[2 * i] - phi), 0.5f);
    }
}

extern "C" void kernel_launch(void* const* d_in, const int* in_sizes, int n_in,
                              void* d_out, int out_size) {
    const float* x = (const float*)d_in[0];    // [B, 2] float32
    const float* w = (const float*)d_in[1];    // [N_LAYERS, 2] float32
    float* out = (float*)d_out;                // [B, 1] float32

    int n = in_sizes[0] / 2;                   // samples B
    int n_layers = in_sizes[1] / 2;

    long long threads = ((long long)n + 7) / 8;
    int blocks = (int)((threads + 255) / 256);
    qnet_kernel<<<blocks, 256>>>(x, out, n, w, n_layers);
}

// round 11
// speedup vs baseline: 1.0632x; 1.0474x over previous
#include <cuda_runtime.h>

// ---------------------------------------------------------------------------
// QuantumNet, fully collapsed via Heisenberg propagation of Z0.
//
//   out = 0.5 + ha*cos(x0) + hb*sin(x0)
//
// O = U^H Z0 U stays in span{Z0, Y0, Z0X1, Y0X1} for any layer count
// (CNOT: Y0<->Y0X1; RX1: identity on the span; RX0 rotates (z,y) pairs).
// On the encoded state <Z0>=cos x0, <Y0>=-sin x0, all X1 terms vanish:
// x1 and the RX1 weights are irrelevant. (Validated R8/R10: rel_err ~1e-7.)
//
// Structure: thread 0 of each block runs the ~20-op weight recurrence and
// broadcasts (ha, hb) via smem; all other threads go straight from their 4
// front-batched LDG.128 to 8x(sincos + 2 FMA) + 2 STG.128. No atan2, no
// prep launch, default cache ops (working set fits in the 126MB L2 across
// graph replays).
// ---------------------------------------------------------------------------

__global__ void __launch_bounds__(256)
qnet_kernel(const float* __restrict__ x, float* __restrict__ out, int n,
            const float* __restrict__ w, int n_layers) {
    __shared__ float sh[2];

    long long t = (long long)blockIdx.x * blockDim.x + threadIdx.x;
    long long base = t * 8;                    // 8 samples per thread
    const bool full = (base + 7) < (long long)n;

    // ---- 1) Front-batched loads: 4x LDG.128 (MLP=4), before the barrier --
    float4 a, b, c, d;
    if (full) {
        const float4* x4 = (const float4*)x;
        a = x4[t * 4 + 0];                     // (x0_0, x1_0, x0_1, x1_1)
        b = x4[t * 4 + 1];
        c = x4[t * 4 + 2];
        d = x4[t * 4 + 3];
    }

    // ---- 2) Thread 0 only: tiny uniform recurrence -> smem ---------------
    if (threadIdx.x == 0) {
        float z = 1.0f, y = 0.0f, zx = 0.0f, yx = 0.0f;
        for (int l = n_layers - 1; l >= 0; l--) {
            float tmp = y; y = yx; yx = tmp;   // CNOT: Y0 <-> Y0X1
            float s, cc;
            __sincosf(__ldg(w + 2 * l), &s, &cc);   // RX0(w_l0) conjugation
            float z2  = fmaf(cc, z,  -s * y);
            float y2  = fmaf(s,  z,   cc * y);
            float zx2 = fmaf(cc, zx, -s * yx);
            float yx2 = fmaf(s,  zx,  cc * yx);
            z = z2; y = y2; zx = zx2; yx = yx2;
        }
        sh[0] = 0.5f * z;                      // ha: coeff of cos(x0)
        sh[1] = -0.5f * y;                     // hb: coeff of sin(x0)
    }
    __syncthreads();
    const float ha = sh[0];
    const float hb = sh[1];

    // ---- 3) Consume: sincos + 2 FMA per sample ---------------------------
    if (full) {
        float S, C;
        float4 o0, o1;
        __sincosf(a.x, &S, &C); o0.x = fmaf(ha, C, fmaf(hb, S, 0.5f));
        __sincosf(a.z, &S, &C); o0.y = fmaf(ha, C, fmaf(hb, S, 0.5f));
        __sincosf(b.x, &S, &C); o0.z = fmaf(ha, C, fmaf(hb, S, 0.5f));
        __sincosf(b.z, &S, &C); o0.w = fmaf(ha, C, fmaf(hb, S, 0.5f));
        __sincosf(c.x, &S, &C); o1.x = fmaf(ha, C, fmaf(hb, S, 0.5f));
        __sincosf(c.z, &S, &C); o1.y = fmaf(ha, C, fmaf(hb, S, 0.5f));
        __sincosf(d.x, &S, &C); o1.z = fmaf(ha, C, fmaf(hb, S, 0.5f));
        __sincosf(d.z, &S, &C); o1.w = fmaf(ha, C, fmaf(hb, S, 0.5f));
        float4* out4 = (float4*)out;
        out4[t * 2 + 0] = o0;
        out4[t * 2 + 1] = o1;
    } else {
        for (long long i = base; i < (long long)n; i++) {
            float S, C;
            __sincosf(x[2 * i], &S, &C);
            out[i] = fmaf(ha, C, fmaf(hb, S, 0.5f));
        }
    }
}

extern "C" void kernel_launch(void* const* d_in, const int* in_sizes, int n_in,
                              void* d_out, int out_size) {
    const float* x = (const float*)d_in[0];    // [B, 2] float32
    const float* w = (const float*)d_in[1];    // [N_LAYERS, 2] float32
    float* out = (float*)d_out;                // [B, 1] float32

    int n = in_sizes[0] / 2;                   // samples B
    int n_layers = in_sizes[1] / 2;

    long long threads = ((long long)n + 7) / 8;
    int blocks = (int)((threads + 255) / 256);
    qnet_kernel<<<blocks, 256>>>(x, out, n, w, n_layers);
}